// round 2
// baseline (speedup 1.0000x reference)
#include <cuda_runtime.h>
#include <cuda_bf16.h>
#include <math.h>

// ---------------------------------------------------------------------------
// GPT2 attention block, fp32 baseline.
//   x[4096,1024] @ W_attn[1024,3072] + b_attn -> qkv
//   16-head causal flash attention (D=64)     -> att[4096,1024]
//   att @ W_proj[1024,1024] + b_proj          -> out
// ---------------------------------------------------------------------------

#define TT      4096
#define CC      1024
#define NHEAD   16
#define HDIM    64
#define SCALE   0.125f   // 1/sqrt(64)

// Scratch (allocation-free rule: __device__ globals)
__device__ float g_qkv[TT * 3 * CC];   // [t][0:1024]=q  [1024:2048]=k  [2048:3072]=v
__device__ float g_att[TT * CC];       // [t][h*64+d]

// ---------------------------------------------------------------------------
// Tiled SGEMM with bias: C[M,N] = A[M,K] @ B[K,N] + bias[N]
// BM=BN=128, BK=16, 256 threads, 8x8 per thread. All dims divide tiles here.
// ---------------------------------------------------------------------------
#define GBM 128
#define GBN 128
#define GBK 16

__global__ __launch_bounds__(256)
void sgemm_bias(const float* __restrict__ A, const float* __restrict__ B,
                const float* __restrict__ bias, float* __restrict__ C,
                int M, int N, int K)
{
    __shared__ float As[GBK][GBM];   // transposed A tile
    __shared__ float Bs[GBK][GBN];

    const int tid = threadIdx.x;          // 0..255
    const int tx  = tid & 15;             // col group
    const int ty  = tid >> 4;             // row group
    const int bm  = blockIdx.y * GBM;
    const int bn  = blockIdx.x * GBN;

    float acc[8][8];
    #pragma unroll
    for (int i = 0; i < 8; i++)
        #pragma unroll
        for (int j = 0; j < 8; j++) acc[i][j] = 0.0f;

    for (int k0 = 0; k0 < K; k0 += GBK) {
        // Load A tile (128x16) as 512 float4; store transposed.
        #pragma unroll
        for (int it = 0; it < 2; it++) {
            int idx = tid + it * 256;              // 0..511
            int r   = idx >> 2;                    // 0..127
            int c4  = (idx & 3) << 2;              // 0,4,8,12
            float4 v = *(const float4*)&A[(size_t)(bm + r) * K + k0 + c4];
            As[c4 + 0][r] = v.x; As[c4 + 1][r] = v.y;
            As[c4 + 2][r] = v.z; As[c4 + 3][r] = v.w;
        }
        // Load B tile (16x128) as 512 float4, direct.
        #pragma unroll
        for (int it = 0; it < 2; it++) {
            int idx = tid + it * 256;
            int r   = idx >> 5;                    // 0..15
            int c4  = (idx & 31) << 2;             // 0..124
            *(float4*)&Bs[r][c4] =
                *(const float4*)&B[(size_t)(k0 + r) * N + bn + c4];
        }
        __syncthreads();

        #pragma unroll
        for (int kk = 0; kk < GBK; kk++) {
            float a[8], b[8];
            #pragma unroll
            for (int i = 0; i < 8; i += 4) {
                float4 v = *(const float4*)&As[kk][ty * 8 + i];
                a[i] = v.x; a[i+1] = v.y; a[i+2] = v.z; a[i+3] = v.w;
            }
            #pragma unroll
            for (int j = 0; j < 8; j += 4) {
                float4 v = *(const float4*)&Bs[kk][tx * 8 + j];
                b[j] = v.x; b[j+1] = v.y; b[j+2] = v.z; b[j+3] = v.w;
            }
            #pragma unroll
            for (int i = 0; i < 8; i++)
                #pragma unroll
                for (int j = 0; j < 8; j++)
                    acc[i][j] += a[i] * b[j];
        }
        __syncthreads();
    }

    #pragma unroll
    for (int i = 0; i < 8; i++) {
        int row = bm + ty * 8 + i;
        #pragma unroll
        for (int j = 0; j < 8; j += 4) {
            int col = bn + tx * 8 + j;
            float4 v;
            v.x = acc[i][j]     + bias[col];
            v.y = acc[i][j + 1] + bias[col + 1];
            v.z = acc[i][j + 2] + bias[col + 2];
            v.w = acc[i][j + 3] + bias[col + 3];
            *(float4*)&C[(size_t)row * N + col] = v;
        }
    }
}

// ---------------------------------------------------------------------------
// Causal flash attention. One block = 128 q rows of one head; 1 thread/row.
// q, acc in registers; K/V tiles (64x64) + S tile (transposed, [64][128]) in
// dynamic smem (64 KB total). Two-phase per tile: scores->smem + tile max,
// then exp/accumulate. Heavy q-tiles launched first (causal balance).
// ---------------------------------------------------------------------------
#define BQ  128
#define BKV 64

__global__ __launch_bounds__(BQ)
void flash_attn_kernel()
{
    extern __shared__ float smem[];
    float* Ks = smem;                    // [BKV][HDIM]
    float* Vs = smem + BKV * HDIM;       // [BKV][HDIM]
    float* Ss = smem + 2 * BKV * HDIM;   // [BKV][BQ]  (transposed scores)

    const int h  = blockIdx.y;
    const int qt = (int)gridDim.x - 1 - (int)blockIdx.x;   // heavy first
    const int q0 = qt * BQ;
    const int t  = threadIdx.x;                             // 0..127
    const int q_idx = q0 + t;

    // Load q row into registers.
    float q[HDIM];
    {
        const float* qrow = g_qkv + (size_t)q_idx * (3 * CC) + h * HDIM;
        #pragma unroll
        for (int d = 0; d < HDIM; d += 4) {
            float4 v = *(const float4*)&qrow[d];
            q[d] = v.x; q[d+1] = v.y; q[d+2] = v.z; q[d+3] = v.w;
        }
    }

    float acc[HDIM];
    #pragma unroll
    for (int d = 0; d < HDIM; d++) acc[d] = 0.0f;
    float m = -1e30f, l = 0.0f;

    const int n_tiles = q0 / BKV + BQ / BKV;   // tiles covering keys [0, q0+BQ)

    for (int kt = 0; kt < n_tiles; kt++) {
        const int k0 = kt * BKV;

        // Cooperative K/V tile load: 64 rows x 64, each thread half a row.
        {
            int r = t >> 1;
            int c = (t & 1) * 32;
            const float* krow = g_qkv + (size_t)(k0 + r) * (3 * CC) + CC     + h * HDIM + c;
            const float* vrow = g_qkv + (size_t)(k0 + r) * (3 * CC) + 2 * CC + h * HDIM + c;
            #pragma unroll
            for (int i = 0; i < 32; i += 4) {
                *(float4*)&Ks[r * HDIM + c + i] = *(const float4*)&krow[i];
                *(float4*)&Vs[r * HDIM + c + i] = *(const float4*)&vrow[i];
            }
        }
        __syncthreads();

        // Per-thread causal bound inside this tile.
        int j_end = q_idx - k0 + 1;
        if (j_end > BKV) j_end = BKV;

        // Phase 1: scores -> Ss (transposed: conflict-free), running tile max.
        float tmax = -1e30f;
        for (int j = 0; j < j_end; j++) {
            float s = 0.0f;
            #pragma unroll
            for (int d = 0; d < HDIM; d += 4) {
                float4 kv = *(const float4*)&Ks[j * HDIM + d];  // broadcast
                s += q[d] * kv.x + q[d+1] * kv.y + q[d+2] * kv.z + q[d+3] * kv.w;
            }
            s *= SCALE;
            Ss[j * BQ + t] = s;
            tmax = fmaxf(tmax, s);
        }

        // Online softmax rescale.
        float m_new = fmaxf(m, tmax);
        float alpha = __expf(m - m_new);
        l *= alpha;
        #pragma unroll
        for (int d = 0; d < HDIM; d++) acc[d] *= alpha;

        // Phase 2: exp + PV accumulate.
        for (int j = 0; j < j_end; j++) {
            float p = __expf(Ss[j * BQ + t] - m_new);
            l += p;
            #pragma unroll
            for (int d = 0; d < HDIM; d += 4) {
                float4 vv = *(const float4*)&Vs[j * HDIM + d];  // broadcast
                acc[d]   += p * vv.x;
                acc[d+1] += p * vv.y;
                acc[d+2] += p * vv.z;
                acc[d+3] += p * vv.w;
            }
        }
        m = m_new;
        __syncthreads();
    }

    const float inv_l = 1.0f / l;
    float* orow = g_att + (size_t)q_idx * CC + h * HDIM;
    #pragma unroll
    for (int d = 0; d < HDIM; d += 4) {
        float4 v;
        v.x = acc[d]   * inv_l;
        v.y = acc[d+1] * inv_l;
        v.z = acc[d+2] * inv_l;
        v.w = acc[d+3] * inv_l;
        *(float4*)&orow[d] = v;
    }
}

// ---------------------------------------------------------------------------
// Launch
// ---------------------------------------------------------------------------
extern "C" void kernel_launch(void* const* d_in, const int* in_sizes, int n_in,
                              void* d_out, int out_size)
{
    const float* x      = (const float*)d_in[0];
    const float* W_attn = (const float*)d_in[1];
    const float* b_attn = (const float*)d_in[2];
    const float* W_proj = (const float*)d_in[3];
    const float* b_proj = (const float*)d_in[4];
    float*       out    = (float*)d_out;

    void *qkv_ptr, *att_ptr;
    cudaGetSymbolAddress(&qkv_ptr, g_qkv);
    cudaGetSymbolAddress(&att_ptr, g_att);
    float* qkv = (float*)qkv_ptr;
    float* att = (float*)att_ptr;

    const int FLASH_SMEM = (2 * BKV * HDIM + BKV * BQ) * (int)sizeof(float); // 65536
    cudaFuncSetAttribute(flash_attn_kernel,
                         cudaFuncAttributeMaxDynamicSharedMemorySize, FLASH_SMEM);

    // 1) QKV projection: [4096,1024] @ [1024,3072] + b_attn
    {
        dim3 grid(3 * CC / GBN, TT / GBM);
        sgemm_bias<<<grid, 256>>>(x, W_attn, b_attn, qkv, TT, 3 * CC, CC);
    }

    // 2) Causal flash attention
    {
        dim3 grid(TT / BQ, NHEAD);
        flash_attn_kernel<<<grid, BQ, FLASH_SMEM>>>();
    }

    // 3) Output projection: [4096,1024] @ [1024,1024] + b_proj
    {
        dim3 grid(CC / GBN, TT / GBM);
        sgemm_bias<<<grid, 256>>>(att, W_proj, b_proj, out, TT, CC, CC);
    }
}

// round 3
// speedup vs baseline: 1.2271x; 1.2271x over previous
#include <cuda_runtime.h>
#include <cuda_bf16.h>
#include <math.h>

// ---------------------------------------------------------------------------
// GPT2 attention block, fp32 + packed f32x2 (FFMA2) version.
//   x[4096,1024] @ W_attn[1024,3072] + b_attn -> qkv
//   16-head causal flash attention (D=64)     -> att[4096,1024]
//   att @ W_proj[1024,1024] + b_proj          -> out
// ---------------------------------------------------------------------------

#define TT      4096
#define CC      1024
#define NHEAD   16
#define HDIM    64
#define SCALE   0.125f   // 1/sqrt(64)

__device__ float g_qkv[TT * 3 * CC];
__device__ float g_att[TT * CC];

typedef unsigned long long u64t;

// ---- packed f32x2 helpers (sm_100a) ---------------------------------------
__device__ __forceinline__ u64t fma2(u64t a, u64t b, u64t c) {
    u64t d;
    asm("fma.rn.f32x2 %0, %1, %2, %3;" : "=l"(d) : "l"(a), "l"(b), "l"(c));
    return d;
}
__device__ __forceinline__ u64t mul2(u64t a, u64t b) {
    u64t d;
    asm("mul.rn.f32x2 %0, %1, %2;" : "=l"(d) : "l"(a), "l"(b));
    return d;
}
__device__ __forceinline__ u64t dup2(float x) {
    u64t d; unsigned int u = __float_as_uint(x);
    asm("mov.b64 %0, {%1, %1};" : "=l"(d) : "r"(u));
    return d;
}
__device__ __forceinline__ float2 unpk(u64t v) {
    unsigned int lo, hi;
    asm("mov.b64 {%0, %1}, %2;" : "=r"(lo), "=r"(hi) : "l"(v));
    return make_float2(__uint_as_float(lo), __uint_as_float(hi));
}

// ---------------------------------------------------------------------------
// Tiled SGEMM + bias with f32x2 accumulators.
// BM=BN=128, BK=16, 256 threads, 8x8 per thread (stored as 4x8 f32x2 pairs
// packed along the row dimension i; a-pairs come contiguous from transposed
// As, b is duplicated into both halves).
// ---------------------------------------------------------------------------
#define GBM 128
#define GBN 128
#define GBK 16

__global__ __launch_bounds__(256)
void sgemm_bias(const float* __restrict__ A, const float* __restrict__ B,
                const float* __restrict__ bias, float* __restrict__ C,
                int M, int N, int K)
{
    __shared__ float As[GBK][GBM];   // transposed A tile
    __shared__ float Bs[GBK][GBN];

    const int tid = threadIdx.x;
    const int tx  = tid & 15;
    const int ty  = tid >> 4;
    const int bm  = blockIdx.y * GBM;
    const int bn  = blockIdx.x * GBN;

    u64t accp[4][8];
    #pragma unroll
    for (int ii = 0; ii < 4; ii++)
        #pragma unroll
        for (int j = 0; j < 8; j++) accp[ii][j] = 0ull;

    for (int k0 = 0; k0 < K; k0 += GBK) {
        #pragma unroll
        for (int it = 0; it < 2; it++) {
            int idx = tid + it * 256;
            int r   = idx >> 2;
            int c4  = (idx & 3) << 2;
            float4 v = *(const float4*)&A[(size_t)(bm + r) * K + k0 + c4];
            As[c4 + 0][r] = v.x; As[c4 + 1][r] = v.y;
            As[c4 + 2][r] = v.z; As[c4 + 3][r] = v.w;
        }
        #pragma unroll
        for (int it = 0; it < 2; it++) {
            int idx = tid + it * 256;
            int r   = idx >> 5;
            int c4  = (idx & 31) << 2;
            *(float4*)&Bs[r][c4] =
                *(const float4*)&B[(size_t)(k0 + r) * N + bn + c4];
        }
        __syncthreads();

        #pragma unroll
        for (int kk = 0; kk < GBK; kk++) {
            // a pairs: rows (2ii, 2ii+1), contiguous in transposed As
            u64t ap[4];
            const u64t* pa = (const u64t*)&As[kk][ty * 8];
            #pragma unroll
            for (int ii = 0; ii < 4; ii++) ap[ii] = pa[ii];
            // b duplicated into both halves
            u64t bd[8];
            #pragma unroll
            for (int j = 0; j < 8; j += 4) {
                float4 v = *(const float4*)&Bs[kk][tx * 8 + j];
                bd[j]     = dup2(v.x);
                bd[j + 1] = dup2(v.y);
                bd[j + 2] = dup2(v.z);
                bd[j + 3] = dup2(v.w);
            }
            #pragma unroll
            for (int ii = 0; ii < 4; ii++)
                #pragma unroll
                for (int j = 0; j < 8; j++)
                    accp[ii][j] = fma2(ap[ii], bd[j], accp[ii][j]);
        }
        __syncthreads();
    }

    #pragma unroll
    for (int ii = 0; ii < 4; ii++) {
        int row0 = bm + ty * 8 + 2 * ii;
        float lo[8], hi[8];
        #pragma unroll
        for (int j = 0; j < 8; j++) {
            float2 v = unpk(accp[ii][j]);
            lo[j] = v.x; hi[j] = v.y;
        }
        #pragma unroll
        for (int j = 0; j < 8; j += 4) {
            int col = bn + tx * 8 + j;
            float b0 = bias[col], b1 = bias[col + 1], b2 = bias[col + 2], b3 = bias[col + 3];
            float4 v0 = make_float4(lo[j] + b0, lo[j+1] + b1, lo[j+2] + b2, lo[j+3] + b3);
            float4 v1 = make_float4(hi[j] + b0, hi[j+1] + b1, hi[j+2] + b2, hi[j+3] + b3);
            *(float4*)&C[(size_t)row0 * N + col]       = v0;
            *(float4*)&C[(size_t)(row0 + 1) * N + col] = v1;
        }
    }
}

// ---------------------------------------------------------------------------
// Register-blocked causal flash attention.
// Block = 128 q rows x one head, 256 threads (16x16 grid, 8x8 S per thread).
// S GEMM and PV GEMM both use f32x2. P staged once through padded smem.
// Row max/sum reduced via shfl.xor within 16-thread row groups.
// smem: Q^T[64][128] + K^T[64][128] + V[128][64] + P[128][132] = 162 KB.
// ---------------------------------------------------------------------------
#define AT_TH   256
#define PSTR    132

__global__ __launch_bounds__(AT_TH)
void flash_attn_kernel()
{
    extern __shared__ float smem[];
    float* Qs = smem;                     // [64][128]  (Q^T)
    float* Ks = Qs + HDIM * 128;          // [64][128]  (K^T)
    float* Vs = Ks + HDIM * 128;          // [128][64]
    float* Ps = Vs + 128 * HDIM;          // [128][PSTR]

    const int h   = blockIdx.y;
    const int qt  = (int)gridDim.x - 1 - (int)blockIdx.x;   // heavy first
    const int q0  = qt * 128;
    const int tid = threadIdx.x;
    const int tx  = tid & 15;
    const int ty  = tid >> 4;

    // ---- load Q^T tile (transpose during store) ----
    {
        int r  = tid >> 1;
        int c0 = (tid & 1) * 32;
        const float* qrow = g_qkv + (size_t)(q0 + r) * (3 * CC) + h * HDIM + c0;
        #pragma unroll
        for (int i = 0; i < 32; i += 4) {
            float4 v = *(const float4*)&qrow[i];
            Qs[(c0 + i + 0) * 128 + r] = v.x;
            Qs[(c0 + i + 1) * 128 + r] = v.y;
            Qs[(c0 + i + 2) * 128 + r] = v.z;
            Qs[(c0 + i + 3) * 128 + r] = v.w;
        }
    }

    u64t Op[8][2];
    #pragma unroll
    for (int i = 0; i < 8; i++) { Op[i][0] = 0ull; Op[i][1] = 0ull; }
    float mrow[8], lrow[8];
    #pragma unroll
    for (int i = 0; i < 8; i++) { mrow[i] = -1e30f; lrow[i] = 0.0f; }

    __syncthreads();

    for (int kt = 0; kt <= qt; kt++) {
        const int k0 = kt * 128;

        // ---- load K^T (transposed) and V tiles ----
        {
            int r  = tid >> 1;
            int c0 = (tid & 1) * 32;
            const float* kro = g_qkv + (size_t)(k0 + r) * (3 * CC) + CC     + h * HDIM + c0;
            const float* vro = g_qkv + (size_t)(k0 + r) * (3 * CC) + 2 * CC + h * HDIM + c0;
            #pragma unroll
            for (int i = 0; i < 32; i += 4) {
                float4 kv = *(const float4*)&kro[i];
                Ks[(c0 + i + 0) * 128 + r] = kv.x;
                Ks[(c0 + i + 1) * 128 + r] = kv.y;
                Ks[(c0 + i + 2) * 128 + r] = kv.z;
                Ks[(c0 + i + 3) * 128 + r] = kv.w;
                *(float4*)&Vs[r * HDIM + c0 + i] = *(const float4*)&vro[i];
            }
        }
        __syncthreads();

        // ---- S = Q K^T, f32x2 packed along columns ----
        u64t Sp[8][4];
        #pragma unroll
        for (int i = 0; i < 8; i++)
            #pragma unroll
            for (int jj = 0; jj < 4; jj++) Sp[i][jj] = 0ull;

        #pragma unroll 4
        for (int d = 0; d < HDIM; d++) {
            u64t bp[4];
            const u64t* pb = (const u64t*)&Ks[d * 128 + tx * 8];
            bp[0] = pb[0]; bp[1] = pb[1]; bp[2] = pb[2]; bp[3] = pb[3];
            const float* qa = &Qs[d * 128 + ty * 8];
            #pragma unroll
            for (int i = 0; i < 8; i++) {
                u64t ad = dup2(qa[i]);
                #pragma unroll
                for (int jj = 0; jj < 4; jj++)
                    Sp[i][jj] = fma2(ad, bp[jj], Sp[i][jj]);
            }
        }

        // ---- unpack + scale + mask ----
        float p[8][8];
        #pragma unroll
        for (int i = 0; i < 8; i++)
            #pragma unroll
            for (int jj = 0; jj < 4; jj++) {
                float2 v = unpk(Sp[i][jj]);
                p[i][2 * jj]     = v.x * SCALE;
                p[i][2 * jj + 1] = v.y * SCALE;
            }
        if (kt == qt) {
            #pragma unroll
            for (int i = 0; i < 8; i++) {
                int row = ty * 8 + i;
                #pragma unroll
                for (int j = 0; j < 8; j++)
                    if (tx * 8 + j > row) p[i][j] = -1e30f;
            }
        }

        // ---- online softmax ----
        #pragma unroll
        for (int i = 0; i < 8; i++) {
            float rm = p[i][0];
            #pragma unroll
            for (int j = 1; j < 8; j++) rm = fmaxf(rm, p[i][j]);
            #pragma unroll
            for (int off = 8; off >= 1; off >>= 1)
                rm = fmaxf(rm, __shfl_xor_sync(0xffffffffu, rm, off));

            float m_new = fmaxf(mrow[i], rm);
            float alpha = __expf(mrow[i] - m_new);
            mrow[i] = m_new;
            u64t a2 = dup2(alpha);
            Op[i][0] = mul2(Op[i][0], a2);
            Op[i][1] = mul2(Op[i][1], a2);

            float rs = 0.0f;
            #pragma unroll
            for (int j = 0; j < 8; j++) {
                float e = __expf(p[i][j] - m_new);
                p[i][j] = e;
                rs += e;
            }
            #pragma unroll
            for (int off = 8; off >= 1; off >>= 1)
                rs += __shfl_xor_sync(0xffffffffu, rs, off);
            lrow[i] = lrow[i] * alpha + rs;

            // stage P row-segment to smem
            *(float4*)&Ps[(ty * 8 + i) * PSTR + tx * 8]     =
                make_float4(p[i][0], p[i][1], p[i][2], p[i][3]);
            *(float4*)&Ps[(ty * 8 + i) * PSTR + tx * 8 + 4] =
                make_float4(p[i][4], p[i][5], p[i][6], p[i][7]);
        }
        __syncthreads();

        // ---- O += P V, f32x2 packed along V columns ----
        #pragma unroll 2
        for (int kk = 0; kk < 128; kk++) {
            u64t vp0, vp1;
            const u64t* pv = (const u64t*)&Vs[kk * HDIM + tx * 4];
            vp0 = pv[0]; vp1 = pv[1];
            #pragma unroll
            for (int i = 0; i < 8; i++) {
                u64t ad = dup2(Ps[(ty * 8 + i) * PSTR + kk]);
                Op[i][0] = fma2(ad, vp0, Op[i][0]);
                Op[i][1] = fma2(ad, vp1, Op[i][1]);
            }
        }
        __syncthreads();   // PV done before next tile overwrites Ks/Vs/Ps
    }

    // ---- epilogue: normalize + store ----
    #pragma unroll
    for (int i = 0; i < 8; i++) {
        float inv = 1.0f / lrow[i];
        float2 a = unpk(Op[i][0]);
        float2 b = unpk(Op[i][1]);
        float4 o = make_float4(a.x * inv, a.y * inv, b.x * inv, b.y * inv);
        *(float4*)&g_att[(size_t)(q0 + ty * 8 + i) * CC + h * HDIM + tx * 4] = o;
    }
}

// ---------------------------------------------------------------------------
// Launch
// ---------------------------------------------------------------------------
extern "C" void kernel_launch(void* const* d_in, const int* in_sizes, int n_in,
                              void* d_out, int out_size)
{
    const float* x      = (const float*)d_in[0];
    const float* W_attn = (const float*)d_in[1];
    const float* b_attn = (const float*)d_in[2];
    const float* W_proj = (const float*)d_in[3];
    const float* b_proj = (const float*)d_in[4];
    float*       out    = (float*)d_out;

    void *qkv_ptr, *att_ptr;
    cudaGetSymbolAddress(&qkv_ptr, g_qkv);
    cudaGetSymbolAddress(&att_ptr, g_att);
    float* qkv = (float*)qkv_ptr;
    float* att = (float*)att_ptr;

    const int FLASH_SMEM = (2 * HDIM * 128 + 128 * HDIM + 128 * PSTR) * (int)sizeof(float);
    cudaFuncSetAttribute(flash_attn_kernel,
                         cudaFuncAttributeMaxDynamicSharedMemorySize, FLASH_SMEM);

    // 1) QKV projection
    {
        dim3 grid(3 * CC / GBN, TT / GBM);
        sgemm_bias<<<grid, 256>>>(x, W_attn, b_attn, qkv, TT, 3 * CC, CC);
    }
    // 2) Causal flash attention
    {
        dim3 grid(TT / 128, NHEAD);
        flash_attn_kernel<<<grid, AT_TH, FLASH_SMEM>>>();
    }
    // 3) Output projection
    {
        dim3 grid(CC / GBN, TT / GBM);
        sgemm_bias<<<grid, 256>>>(att, W_proj, b_proj, out, TT, CC, CC);
    }
}

// round 4
// speedup vs baseline: 2.7075x; 2.2065x over previous
#include <cuda_runtime.h>
#include <cuda_bf16.h>
#include <math.h>

// ---------------------------------------------------------------------------
// GPT2 attention block — tf32 tensor-core (mma.sync.m16n8k8) version.
//   x[4096,1024] @ W_attn[1024,3072] + b_attn -> qkv
//   16-head causal flash attention (D=64)     -> att[4096,1024]
//   att @ W_proj[1024,1024] + b_proj          -> out
// ---------------------------------------------------------------------------

#define TT      4096
#define CC      1024
#define NHEAD   16
#define HDIM    64
#define SCALE   0.125f

__device__ float g_qkv[TT * 3 * CC];
__device__ float g_att[TT * CC];

// ---- tf32 helpers ---------------------------------------------------------
__device__ __forceinline__ unsigned cvt_tf32(float x) {
    unsigned u;
    asm("cvt.rna.tf32.f32 %0, %1;" : "=r"(u) : "f"(x));
    return u;
}

__device__ __forceinline__ void mma_tf32(float* d, const unsigned* a,
                                         unsigned b0, unsigned b1) {
    asm volatile(
        "mma.sync.aligned.m16n8k8.row.col.f32.tf32.tf32.f32 "
        "{%0,%1,%2,%3}, {%4,%5,%6,%7}, {%8,%9}, {%0,%1,%2,%3};"
        : "+f"(d[0]), "+f"(d[1]), "+f"(d[2]), "+f"(d[3])
        : "r"(a[0]), "r"(a[1]), "r"(a[2]), "r"(a[3]), "r"(b0), "r"(b1));
}

// ---------------------------------------------------------------------------
// Tensor-core GEMM + bias: C[M,N] = A[M,K] @ B[K,N] + bias
// 128x128x32 block tile, 256 threads = 8 warps (2x4), 64x32 per warp.
// A stored transposed [k][m] (stride 132), B direct [k][n] (stride 132).
// ---------------------------------------------------------------------------
#define SSTR 132

__global__ __launch_bounds__(256)
void gemm_tc(const float* __restrict__ A, const float* __restrict__ B,
             const float* __restrict__ bias, float* __restrict__ C,
             int M, int N, int K)
{
    __shared__ unsigned As[32 * SSTR];   // [k][m]
    __shared__ unsigned Bs[32 * SSTR];   // [k][n]

    const int tid  = threadIdx.x;
    const int lane = tid & 31;
    const int w    = tid >> 5;
    const int wm   = w >> 2;          // 0..1
    const int wn   = w & 3;           // 0..3
    const int bm   = blockIdx.y * 128;
    const int bn   = blockIdx.x * 128;

    float d[4][4][4];
    #pragma unroll
    for (int im = 0; im < 4; im++)
        #pragma unroll
        for (int jn = 0; jn < 4; jn++)
            #pragma unroll
            for (int r = 0; r < 4; r++) d[im][jn][r] = 0.0f;

    for (int k0 = 0; k0 < K; k0 += 32) {
        // A tile 128x32 -> As[k][m] (transposed, cvt to tf32)
        #pragma unroll
        for (int i = 0; i < 4; i++) {
            int idx = tid + i * 256;          // 0..1023
            int r   = idx >> 3;               // m row 0..127
            int c4  = (idx & 7) * 4;          // k col
            float4 v = *(const float4*)&A[(size_t)(bm + r) * K + k0 + c4];
            As[(c4 + 0) * SSTR + r] = cvt_tf32(v.x);
            As[(c4 + 1) * SSTR + r] = cvt_tf32(v.y);
            As[(c4 + 2) * SSTR + r] = cvt_tf32(v.z);
            As[(c4 + 3) * SSTR + r] = cvt_tf32(v.w);
        }
        // B tile 32x128 -> Bs[k][n] (direct, cvt)
        #pragma unroll
        for (int i = 0; i < 4; i++) {
            int idx = tid + i * 256;
            int r   = idx >> 5;               // k 0..31
            int c4  = (idx & 31) * 4;         // n
            float4 v = *(const float4*)&B[(size_t)(k0 + r) * N + bn + c4];
            uint4 u;
            u.x = cvt_tf32(v.x); u.y = cvt_tf32(v.y);
            u.z = cvt_tf32(v.z); u.w = cvt_tf32(v.w);
            *(uint4*)&Bs[r * SSTR + c4] = u;
        }
        __syncthreads();

        #pragma unroll
        for (int ks = 0; ks < 4; ks++) {
            const int kk = ks * 8 + (lane & 3);
            const int mr = wm * 64 + (lane >> 2);
            unsigned a[4][4];
            #pragma unroll
            for (int im = 0; im < 4; im++) {
                a[im][0] = As[kk * SSTR + mr + im * 16];
                a[im][1] = As[kk * SSTR + mr + im * 16 + 8];
                a[im][2] = As[(kk + 4) * SSTR + mr + im * 16];
                a[im][3] = As[(kk + 4) * SSTR + mr + im * 16 + 8];
            }
            const int nc = wn * 32 + (lane >> 2);
            unsigned b[4][2];
            #pragma unroll
            for (int jn = 0; jn < 4; jn++) {
                b[jn][0] = Bs[kk * SSTR + nc + jn * 8];
                b[jn][1] = Bs[(kk + 4) * SSTR + nc + jn * 8];
            }
            #pragma unroll
            for (int im = 0; im < 4; im++)
                #pragma unroll
                for (int jn = 0; jn < 4; jn++)
                    mma_tf32(d[im][jn], a[im], b[jn][0], b[jn][1]);
        }
        __syncthreads();
    }

    // epilogue + bias
    #pragma unroll
    for (int im = 0; im < 4; im++) {
        int r_lo = bm + wm * 64 + im * 16 + (lane >> 2);
        #pragma unroll
        for (int jn = 0; jn < 4; jn++) {
            int col = bn + wn * 32 + jn * 8 + 2 * (lane & 3);
            float b0 = bias[col], b1 = bias[col + 1];
            float2 v0 = make_float2(d[im][jn][0] + b0, d[im][jn][1] + b1);
            float2 v1 = make_float2(d[im][jn][2] + b0, d[im][jn][3] + b1);
            *(float2*)&C[(size_t)r_lo * N + col]       = v0;
            *(float2*)&C[(size_t)(r_lo + 8) * N + col] = v1;
        }
    }
}

// ---------------------------------------------------------------------------
// Tensor-core causal flash attention.
// Block = 128 q rows x one head, 256 threads = 8 warps; warp w owns q rows
// [16w, 16w+16). S and PV via mma.sync tf32. P round-trips through SMEM
// (warp-local rows => __syncwarp only).
// ---------------------------------------------------------------------------
#define QS_STR 132
#define VS_STR 68
#define PS_STR 132

__global__ __launch_bounds__(256)
void flash_attn_tc()
{
    extern __shared__ unsigned smem[];
    unsigned* Qs  = smem;                        // [64][132]  Q^T (tf32)
    unsigned* Ksm = Qs + HDIM * QS_STR;          // [64][132]  K^T (tf32)
    unsigned* Vsm = Ksm + HDIM * QS_STR;         // [128][68]  V   (tf32)
    unsigned* Psm = Vsm + 128 * VS_STR;          // [128][132] P   (tf32)

    const int h    = blockIdx.y;
    const int qt   = (int)gridDim.x - 1 - (int)blockIdx.x;  // heavy first
    const int q0   = qt * 128;
    const int tid  = threadIdx.x;
    const int lane = tid & 31;
    const int w    = tid >> 5;

    // ---- load Q tile, transposed, cvt tf32 ----
    #pragma unroll
    for (int i = 0; i < 8; i++) {
        int idx = tid + i * 256;          // 0..2047
        int r   = idx >> 4;               // q row 0..127
        int c4  = (idx & 15) * 4;         // d
        float4 v = *(const float4*)&g_qkv[(size_t)(q0 + r) * (3 * CC) + h * HDIM + c4];
        Qs[(c4 + 0) * QS_STR + r] = cvt_tf32(v.x);
        Qs[(c4 + 1) * QS_STR + r] = cvt_tf32(v.y);
        Qs[(c4 + 2) * QS_STR + r] = cvt_tf32(v.z);
        Qs[(c4 + 3) * QS_STR + r] = cvt_tf32(v.w);
    }

    float o[8][4];
    #pragma unroll
    for (int n = 0; n < 8; n++)
        #pragma unroll
        for (int r = 0; r < 4; r++) o[n][r] = 0.0f;
    float m_lo = -1e30f, m_hi = -1e30f, l_lo = 0.0f, l_hi = 0.0f;

    const int qrl  = lane >> 2;         // row-in-frag
    const int quad = lane & 3;

    for (int kt = 0; kt <= qt; kt++) {
        const int k0 = kt * 128;

        // ---- load K (transposed) and V (direct), cvt tf32 ----
        #pragma unroll
        for (int i = 0; i < 8; i++) {
            int idx = tid + i * 256;
            int r   = idx >> 4;           // key row 0..127
            int c4  = (idx & 15) * 4;     // d
            const float* kro = &g_qkv[(size_t)(k0 + r) * (3 * CC) + CC + h * HDIM + c4];
            float4 kv = *(const float4*)kro;
            Ksm[(c4 + 0) * QS_STR + r] = cvt_tf32(kv.x);
            Ksm[(c4 + 1) * QS_STR + r] = cvt_tf32(kv.y);
            Ksm[(c4 + 2) * QS_STR + r] = cvt_tf32(kv.z);
            Ksm[(c4 + 3) * QS_STR + r] = cvt_tf32(kv.w);
            float4 vv = *(const float4*)(kro + CC);
            uint4 u;
            u.x = cvt_tf32(vv.x); u.y = cvt_tf32(vv.y);
            u.z = cvt_tf32(vv.z); u.w = cvt_tf32(vv.w);
            *(uint4*)&Vsm[r * VS_STR + c4] = u;
        }
        __syncthreads();

        // ---- S = Q K^T (16 rows x 128 cols per warp) ----
        float s[16][4];
        #pragma unroll
        for (int j = 0; j < 16; j++)
            #pragma unroll
            for (int r = 0; r < 4; r++) s[j][r] = 0.0f;

        #pragma unroll
        for (int ks = 0; ks < 8; ks++) {
            const int kk = ks * 8 + quad;
            unsigned a[4];
            a[0] = Qs[kk * QS_STR + w * 16 + qrl];
            a[1] = Qs[kk * QS_STR + w * 16 + qrl + 8];
            a[2] = Qs[(kk + 4) * QS_STR + w * 16 + qrl];
            a[3] = Qs[(kk + 4) * QS_STR + w * 16 + qrl + 8];
            #pragma unroll
            for (int j = 0; j < 16; j++) {
                unsigned b0 = Ksm[kk * QS_STR + j * 8 + qrl];
                unsigned b1 = Ksm[(kk + 4) * QS_STR + j * 8 + qrl];
                mma_tf32(s[j], a, b0, b1);
            }
        }

        // ---- scale + causal mask + row max ----
        float tm_lo = -1e30f, tm_hi = -1e30f;
        #pragma unroll
        for (int j = 0; j < 16; j++) {
            #pragma unroll
            for (int r = 0; r < 4; r++) s[j][r] *= SCALE;
            if (kt == qt) {
                int col  = j * 8 + 2 * quad;
                int rlo  = w * 16 + qrl;
                int rhi  = rlo + 8;
                if (col > rlo)     s[j][0] = -1e30f;
                if (col + 1 > rlo) s[j][1] = -1e30f;
                if (col > rhi)     s[j][2] = -1e30f;
                if (col + 1 > rhi) s[j][3] = -1e30f;
            }
            tm_lo = fmaxf(tm_lo, fmaxf(s[j][0], s[j][1]));
            tm_hi = fmaxf(tm_hi, fmaxf(s[j][2], s[j][3]));
        }
        tm_lo = fmaxf(tm_lo, __shfl_xor_sync(0xffffffffu, tm_lo, 1));
        tm_lo = fmaxf(tm_lo, __shfl_xor_sync(0xffffffffu, tm_lo, 2));
        tm_hi = fmaxf(tm_hi, __shfl_xor_sync(0xffffffffu, tm_hi, 1));
        tm_hi = fmaxf(tm_hi, __shfl_xor_sync(0xffffffffu, tm_hi, 2));

        float mn_lo = fmaxf(m_lo, tm_lo);
        float mn_hi = fmaxf(m_hi, tm_hi);
        float al_lo = __expf(m_lo - mn_lo);
        float al_hi = __expf(m_hi - mn_hi);
        m_lo = mn_lo; m_hi = mn_hi;
        #pragma unroll
        for (int n = 0; n < 8; n++) {
            o[n][0] *= al_lo; o[n][1] *= al_lo;
            o[n][2] *= al_hi; o[n][3] *= al_hi;
        }

        // ---- exp + row sum + stage P (tf32) ----
        float rs_lo = 0.0f, rs_hi = 0.0f;
        const int rlo = w * 16 + qrl;
        #pragma unroll
        for (int j = 0; j < 16; j++) {
            float p0 = __expf(s[j][0] - mn_lo);
            float p1 = __expf(s[j][1] - mn_lo);
            float p2 = __expf(s[j][2] - mn_hi);
            float p3 = __expf(s[j][3] - mn_hi);
            rs_lo += p0 + p1;
            rs_hi += p2 + p3;
            uint2 ulo = make_uint2(cvt_tf32(p0), cvt_tf32(p1));
            uint2 uhi = make_uint2(cvt_tf32(p2), cvt_tf32(p3));
            *(uint2*)&Psm[(size_t)rlo * PS_STR + j * 8 + 2 * quad]       = ulo;
            *(uint2*)&Psm[(size_t)(rlo + 8) * PS_STR + j * 8 + 2 * quad] = uhi;
        }
        rs_lo += __shfl_xor_sync(0xffffffffu, rs_lo, 1);
        rs_lo += __shfl_xor_sync(0xffffffffu, rs_lo, 2);
        rs_hi += __shfl_xor_sync(0xffffffffu, rs_hi, 1);
        rs_hi += __shfl_xor_sync(0xffffffffu, rs_hi, 2);
        l_lo = l_lo * al_lo + rs_lo;
        l_hi = l_hi * al_hi + rs_hi;

        __syncwarp();   // P rows are warp-local; order STS before LDS

        // ---- O += P V ----
        #pragma unroll
        for (int kc = 0; kc < 16; kc++) {
            const int kk = kc * 8 + quad;
            unsigned a[4];
            a[0] = Psm[(size_t)rlo * PS_STR + kk];
            a[1] = Psm[(size_t)(rlo + 8) * PS_STR + kk];
            a[2] = Psm[(size_t)rlo * PS_STR + kk + 4];
            a[3] = Psm[(size_t)(rlo + 8) * PS_STR + kk + 4];
            #pragma unroll
            for (int n = 0; n < 8; n++) {
                unsigned b0 = Vsm[kk * VS_STR + n * 8 + qrl];
                unsigned b1 = Vsm[(kk + 4) * VS_STR + n * 8 + qrl];
                mma_tf32(o[n], a, b0, b1);
            }
        }
        __syncthreads();  // done with Ksm/Vsm before next tile load
    }

    // ---- epilogue ----
    const float inv_lo = 1.0f / l_lo;
    const float inv_hi = 1.0f / l_hi;
    const int rlo = q0 + w * 16 + qrl;
    #pragma unroll
    for (int n = 0; n < 8; n++) {
        int col = h * HDIM + n * 8 + 2 * quad;
        float2 vlo = make_float2(o[n][0] * inv_lo, o[n][1] * inv_lo);
        float2 vhi = make_float2(o[n][2] * inv_hi, o[n][3] * inv_hi);
        *(float2*)&g_att[(size_t)rlo * CC + col]       = vlo;
        *(float2*)&g_att[(size_t)(rlo + 8) * CC + col] = vhi;
    }
}

// ---------------------------------------------------------------------------
// Launch
// ---------------------------------------------------------------------------
extern "C" void kernel_launch(void* const* d_in, const int* in_sizes, int n_in,
                              void* d_out, int out_size)
{
    const float* x      = (const float*)d_in[0];
    const float* W_attn = (const float*)d_in[1];
    const float* b_attn = (const float*)d_in[2];
    const float* W_proj = (const float*)d_in[3];
    const float* b_proj = (const float*)d_in[4];
    float*       out    = (float*)d_out;

    void *qkv_ptr, *att_ptr;
    cudaGetSymbolAddress(&qkv_ptr, g_qkv);
    cudaGetSymbolAddress(&att_ptr, g_att);
    float* qkv = (float*)qkv_ptr;
    float* att = (float*)att_ptr;

    const int FLASH_SMEM =
        (HDIM * QS_STR + HDIM * QS_STR + 128 * VS_STR + 128 * PS_STR) * (int)sizeof(unsigned);
    cudaFuncSetAttribute(flash_attn_tc,
                         cudaFuncAttributeMaxDynamicSharedMemorySize, FLASH_SMEM);

    // 1) QKV projection
    {
        dim3 grid(3 * CC / 128, TT / 128);
        gemm_tc<<<grid, 256>>>(x, W_attn, b_attn, qkv, TT, 3 * CC, CC);
    }
    // 2) Causal flash attention
    {
        dim3 grid(TT / 128, NHEAD);
        flash_attn_tc<<<grid, 256, FLASH_SMEM>>>();
    }
    // 3) Output projection
    {
        dim3 grid(CC / 128, TT / 128);
        gemm_tc<<<grid, 256>>>(att, W_proj, b_proj, out, TT, CC, CC);
    }
}